// round 10
// baseline (speedup 1.0000x reference)
#include <cuda_runtime.h>

#define BB 4
#define NCH 3
#define NCLS 20
#define HH 512
#define WW 512
#define MAXB 50
#define THREADS 256
#define TILE_PIX 1024
#define NTILES 64              // 64*1024 = 65536 >= max box area (255*255)
#define NBOX (BB * MAXB)
#define NITEMS (NBOX * NTILES)
#define GRID 592               // 148 SMs * 4 CTAs -> one wave

__device__ float g_part[GRID];

__global__ __launch_bounds__(THREADS)
void sel_work_kernel(const float* __restrict__ y_fcn,
                     const float* __restrict__ im_data,
                     const int* __restrict__ gt_boxes,
                     const int* __restrict__ num_boxes) {
    const int tid = threadIdx.x;
    const int lane = tid & 31;
    const int warp = tid >> 5;
    const int plane = HH * WW;

    // cache all box metadata + counts in shared (coalesced, once per CTA)
    __shared__ int sbox[NBOX * 5];
    __shared__ int snb[BB];
    for (int i = tid; i < NBOX * 5; i += THREADS) sbox[i] = __ldg(gt_boxes + i);
    if (tid < BB) snb[tid] = __ldg(num_boxes + tid);
    __syncthreads();

    float acc = 0.0f;

    for (int item = blockIdx.x; item < NITEMS; item += GRID) {
        const int boxid = item >> 6;        // / NTILES
        const int tile  = item & (NTILES - 1);
        const int b = boxid / MAXB;
        const int j = boxid - b * MAXB;
        if (j >= snb[b]) continue;

        const int* g = sbox + boxid * 5;
        const int x1 = g[0], y1 = g[1], x2 = g[2], y2 = g[3], cls = g[4];
        const int hgt = y2 - y1;
        const int wid = x2 - x1;
        if (hgt <= 0 || wid <= 0) continue;
        const int area = hgt * wid;
        const int start = tile * TILE_PIX;
        if (start >= area) continue;
        const int end = min(start + TILE_PIX, area);

        const float* im0 = im_data + b * NCH * plane;
        const float* yf0 = y_fcn + (b * NCLS + cls) * NCH * plane;
        const float inv_denom = 1.0f / (float)(NCH * area);

        float a0 = 0.0f, a1 = 0.0f;
        const unsigned uw = (unsigned)wid;
#pragma unroll 4
        for (int idx = start + tid; idx < end; idx += THREADS) {
            const unsigned rr = (unsigned)idx / uw;
            const unsigned cc = (unsigned)idx - rr * uw;
            const int off = (y1 + (int)rr) * WW + x1 + (int)cc;
            const float d0 = __ldg(im0 + off)             - __ldg(yf0 + off);
            const float d1 = __ldg(im0 + plane + off)     - __ldg(yf0 + plane + off);
            const float d2 = __ldg(im0 + 2 * plane + off) - __ldg(yf0 + 2 * plane + off);
            a0 += d0 * d0 + d2 * d2;
            a1 += d1 * d1;
        }
        acc += (a0 + a1) * inv_denom;
    }

    // block reduction
    __shared__ float sm[THREADS / 32];
#pragma unroll
    for (int o = 16; o > 0; o >>= 1)
        acc += __shfl_down_sync(0xffffffffu, acc, o);
    if (lane == 0) sm[warp] = acc;
    __syncthreads();

    if (tid == 0) {
        float s = 0.0f;
#pragma unroll
        for (int w = 0; w < THREADS / 32; w++) s += sm[w];
        g_part[blockIdx.x] = s;   // unconditional: every slot refreshed per call
    }
}

__global__ void sel_final_kernel(const int* __restrict__ num_boxes,
                                 float* __restrict__ out) {
    const int tid = threadIdx.x;
    const int lane = tid & 31;
    const int warp = tid >> 5;

    float s = 0.0f;
    for (int i = tid; i < GRID; i += THREADS) s += g_part[i];

    __shared__ float sm[THREADS / 32];
#pragma unroll
    for (int o = 16; o > 0; o >>= 1)
        s += __shfl_down_sync(0xffffffffu, s, o);
    if (lane == 0) sm[warp] = s;
    __syncthreads();

    if (tid == 0) {
        float tot = 0.0f;
#pragma unroll
        for (int w = 0; w < THREADS / 32; w++) tot += sm[w];
        int nb = 0;
#pragma unroll
        for (int bi = 0; bi < BB; bi++) nb += num_boxes[bi];
        out[0] = tot / (float)nb;
    }
}

extern "C" void kernel_launch(void* const* d_in, const int* in_sizes, int n_in,
                              void* d_out, int out_size) {
    const float* y_fcn     = (const float*)d_in[0];  // [B, NCH*NCLS, H, W]
    const float* im_data   = (const float*)d_in[1];  // [B, NCH, H, W]
    // d_in[2] = im_info (unused)
    const int*   gt_boxes  = (const int*)d_in[3];    // [B, MAXB, 5]
    const int*   num_boxes = (const int*)d_in[4];    // [B]
    float*       out       = (float*)d_out;

    sel_work_kernel<<<GRID, THREADS>>>(y_fcn, im_data, gt_boxes, num_boxes);
    sel_final_kernel<<<1, THREADS>>>(num_boxes, out);
}

// round 11
// speedup vs baseline: 1.1578x; 1.1578x over previous
#include <cuda_runtime.h>

#define BB 4
#define NCH 3
#define NCLS 20
#define HH 512
#define WW 512
#define MAXB 50
#define STRIPS 16
#define THREADS 256
#define NBOX (BB * MAXB)
#define NBLK (NBOX * STRIPS)

__device__ float g_part[NBLK];

__global__ __launch_bounds__(THREADS)
void sel_strip_kernel(const float* __restrict__ y_fcn,
                      const float* __restrict__ im_data,
                      const int* __restrict__ gt_boxes,
                      const int* __restrict__ num_boxes) {
    const int boxid = blockIdx.x;
    const int strip = blockIdx.y;
    const int b = boxid / MAXB;
    const int j = boxid - b * MAXB;
    const int tid = threadIdx.x;
    const int lane = tid & 31;
    const int warp = tid >> 5;
    const int plane = HH * WW;

    float acc = 0.0f;

    if (j < __ldg(num_boxes + b)) {
        const int* g = gt_boxes + boxid * 5;
        const int x1 = __ldg(g), y1 = __ldg(g + 1);
        const int x2 = __ldg(g + 2), y2 = __ldg(g + 3), cls = __ldg(g + 4);
        const int hgt = y2 - y1;
        const int wid = x2 - x1;
        if (hgt > 0 && wid > 0) {
            const int rows_per = (hgt + STRIPS - 1) / STRIPS;
            const int r0 = y1 + strip * rows_per;
            const int r1 = min(r0 + rows_per, y2);
            if (r0 < r1) {
                const int rows = r1 - r0;
                const float* im0 = im_data + b * NCH * plane;
                const float* yf0 = y_fcn + (b * NCLS + cls) * NCH * plane;

                // column split: scalar edges + 16B-aligned quads
                int c_lo = (x1 + 3) & ~3;
                int c_hi = x2 & ~3;
                int e1, e2, nq;
                if (c_hi > c_lo) {
                    nq = (c_hi - c_lo) >> 2;
                    e1 = c_lo - x1;          // 0..3 left edge px
                    e2 = x2 - c_hi;          // 0..3 right edge px
                } else {
                    nq = 0; e1 = wid; e2 = 0; c_hi = x1;  // all-scalar narrow box
                }

                // ---- edge pass: one shot, tid>>3 = row (rows<=16), tid&7 = slot
                {
                    const int rr = tid >> 3;
                    const int k = tid & 7;
                    if (rr < rows) {
                        int col = -1;
                        if (k < e1)              col = x1 + k;
                        else if (k - e1 < e2)    col = c_hi + (k - e1);
                        if (col >= 0) {
                            const int off = (r0 + rr) * WW + col;
                            const float d0 = __ldg(im0 + off)             - __ldg(yf0 + off);
                            const float d1 = __ldg(im0 + plane + off)     - __ldg(yf0 + plane + off);
                            const float d2 = __ldg(im0 + 2 * plane + off) - __ldg(yf0 + 2 * plane + off);
                            acc += d0 * d0 + d1 * d1 + d2 * d2;
                        }
                    }
                }

                // ---- quad pass: float4 over aligned interior
                const int totq = rows * nq;
                const unsigned unq = (unsigned)nq;
                const float4* imA = (const float4*)im0;
                const float4* imB = (const float4*)(im0 + plane);
                const float4* imC = (const float4*)(im0 + 2 * plane);
                const float4* yfA = (const float4*)yf0;
                const float4* yfB = (const float4*)(yf0 + plane);
                const float4* yfC = (const float4*)(yf0 + 2 * plane);
                float a0 = 0.0f, a1 = 0.0f;
#pragma unroll 2
                for (int idx = tid; idx < totq; idx += THREADS) {
                    const unsigned rr = (unsigned)idx / unq;
                    const unsigned qq = (unsigned)idx - rr * unq;
                    const int q = ((r0 + (int)rr) * WW + c_lo) / 4 + (int)qq;
                    const float4 pa = __ldg(imA + q), qa = __ldg(yfA + q);
                    const float4 pb = __ldg(imB + q), qb = __ldg(yfB + q);
                    const float4 pc = __ldg(imC + q), qc = __ldg(yfC + q);
                    float t;
                    t = pa.x - qa.x; a0 += t * t;  t = pa.y - qa.y; a1 += t * t;
                    t = pa.z - qa.z; a0 += t * t;  t = pa.w - qa.w; a1 += t * t;
                    t = pb.x - qb.x; a0 += t * t;  t = pb.y - qb.y; a1 += t * t;
                    t = pb.z - qb.z; a0 += t * t;  t = pb.w - qb.w; a1 += t * t;
                    t = pc.x - qc.x; a0 += t * t;  t = pc.y - qc.y; a1 += t * t;
                    t = pc.z - qc.z; a0 += t * t;  t = pc.w - qc.w; a1 += t * t;
                }
                acc += a0 + a1;
                acc *= 1.0f / (float)(NCH * hgt * wid);
            }
        }
    }

    // block reduction (all CTAs, including empty ones)
    __shared__ float sm[THREADS / 32];
#pragma unroll
    for (int o = 16; o > 0; o >>= 1)
        acc += __shfl_down_sync(0xffffffffu, acc, o);
    if (lane == 0) sm[warp] = acc;
    __syncthreads();

    if (tid == 0) {
        float s = 0.0f;
#pragma unroll
        for (int w = 0; w < THREADS / 32; w++) s += sm[w];
        g_part[boxid * STRIPS + strip] = s;  // unconditional: refreshed every call
    }
}

__global__ void sel_final_kernel(const int* __restrict__ num_boxes,
                                 float* __restrict__ out) {
    const int tid = threadIdx.x;
    const int lane = tid & 31;
    const int warp = tid >> 5;

    float s = 0.0f;
    for (int i = tid; i < NBLK; i += THREADS) s += g_part[i];

    __shared__ float sm[THREADS / 32];
#pragma unroll
    for (int o = 16; o > 0; o >>= 1)
        s += __shfl_down_sync(0xffffffffu, s, o);
    if (lane == 0) sm[warp] = s;
    __syncthreads();

    if (tid == 0) {
        float tot = 0.0f;
#pragma unroll
        for (int w = 0; w < THREADS / 32; w++) tot += sm[w];
        int nb = 0;
#pragma unroll
        for (int bi = 0; bi < BB; bi++) nb += num_boxes[bi];
        out[0] = tot / (float)nb;
    }
}

extern "C" void kernel_launch(void* const* d_in, const int* in_sizes, int n_in,
                              void* d_out, int out_size) {
    const float* y_fcn     = (const float*)d_in[0];  // [B, NCH*NCLS, H, W]
    const float* im_data   = (const float*)d_in[1];  // [B, NCH, H, W]
    // d_in[2] = im_info (unused)
    const int*   gt_boxes  = (const int*)d_in[3];    // [B, MAXB, 5]
    const int*   num_boxes = (const int*)d_in[4];    // [B]
    float*       out       = (float*)d_out;

    dim3 grid(NBOX, STRIPS);
    sel_strip_kernel<<<grid, THREADS>>>(y_fcn, im_data, gt_boxes, num_boxes);
    sel_final_kernel<<<1, THREADS>>>(num_boxes, out);
}

// round 12
// speedup vs baseline: 1.3157x; 1.1364x over previous
#include <cuda_runtime.h>

#define BB 4
#define NCH 3
#define NCLS 20
#define HH 512
#define WW 512
#define MAXB 50
#define STRIPS 8
#define THREADS 256
#define NBOX (BB * MAXB)

__device__ float g_acc;

__global__ void sel_zero_kernel() { g_acc = 0.0f; }

__global__ __launch_bounds__(THREADS)
void sel_strip_kernel(const float* __restrict__ y_fcn,
                      const float* __restrict__ im_data,
                      const int* __restrict__ gt_boxes,
                      const int* __restrict__ num_boxes) {
    const int boxid = blockIdx.x;
    const int strip = blockIdx.y;
    const int b = boxid / MAXB;
    const int j = boxid - b * MAXB;
    const int tid = threadIdx.x;
    const int lane = tid & 31;
    const int warp = tid >> 5;
    const int plane = HH * WW;

    if (j >= __ldg(num_boxes + b)) return;

    const int* g = gt_boxes + boxid * 5;
    const int x1 = __ldg(g), y1 = __ldg(g + 1);
    const int x2 = __ldg(g + 2), y2 = __ldg(g + 3), cls = __ldg(g + 4);
    const int hgt = y2 - y1;
    const int wid = x2 - x1;
    if (hgt <= 0 || wid <= 0) return;

    const int rows_per = (hgt + STRIPS - 1) / STRIPS;
    const int r0 = y1 + strip * rows_per;
    const int r1 = min(r0 + rows_per, y2);
    if (r0 >= r1) return;

    const int rows = r1 - r0;               // <= 32
    const float* im0 = im_data + b * NCH * plane;
    const float* yf0 = y_fcn + (b * NCLS + cls) * NCH * plane;

    // column split: scalar edges + 16B-aligned quads
    int c_lo = (x1 + 3) & ~3;
    int c_hi = x2 & ~3;
    int e1, e2, nq;
    if (c_hi > c_lo) {
        nq = (c_hi - c_lo) >> 2;
        e1 = c_lo - x1;          // 0..3 left edge px
        e2 = x2 - c_hi;          // 0..3 right edge px
    } else {
        nq = 0; e1 = wid; e2 = 0; c_hi = x1;  // all-scalar narrow box
    }

    float acc = 0.0f;

    // ---- edge pass: tid>>3 = row (rows<=32 fits 256/8), tid&7 = slot
    {
        const int rr = tid >> 3;
        const int k = tid & 7;
        if (rr < rows) {
            int col = -1;
            if (k < e1)           col = x1 + k;
            else if (k - e1 < e2) col = c_hi + (k - e1);
            if (col >= 0) {
                const int off = (r0 + rr) * WW + col;
                const float d0 = __ldg(im0 + off)             - __ldg(yf0 + off);
                const float d1 = __ldg(im0 + plane + off)     - __ldg(yf0 + plane + off);
                const float d2 = __ldg(im0 + 2 * plane + off) - __ldg(yf0 + 2 * plane + off);
                acc += d0 * d0 + d1 * d1 + d2 * d2;
            }
        }
    }

    // ---- quad pass: float4 over aligned interior
    const int totq = rows * nq;
    const unsigned unq = (unsigned)nq;
    const float4* imA = (const float4*)im0;
    const float4* imB = (const float4*)(im0 + plane);
    const float4* imC = (const float4*)(im0 + 2 * plane);
    const float4* yfA = (const float4*)yf0;
    const float4* yfB = (const float4*)(yf0 + plane);
    const float4* yfC = (const float4*)(yf0 + 2 * plane);
    float a0 = 0.0f, a1 = 0.0f;
#pragma unroll 2
    for (int idx = tid; idx < totq; idx += THREADS) {
        const unsigned rr = (unsigned)idx / unq;
        const unsigned qq = (unsigned)idx - rr * unq;
        const int q = ((r0 + (int)rr) * WW + c_lo) / 4 + (int)qq;
        const float4 pa = __ldg(imA + q), qa = __ldg(yfA + q);
        const float4 pb = __ldg(imB + q), qb = __ldg(yfB + q);
        const float4 pc = __ldg(imC + q), qc = __ldg(yfC + q);
        float t;
        t = pa.x - qa.x; a0 += t * t;  t = pa.y - qa.y; a1 += t * t;
        t = pa.z - qa.z; a0 += t * t;  t = pa.w - qa.w; a1 += t * t;
        t = pb.x - qb.x; a0 += t * t;  t = pb.y - qb.y; a1 += t * t;
        t = pb.z - qb.z; a0 += t * t;  t = pb.w - qb.w; a1 += t * t;
        t = pc.x - qc.x; a0 += t * t;  t = pc.y - qc.y; a1 += t * t;
        t = pc.z - qc.z; a0 += t * t;  t = pc.w - qc.w; a1 += t * t;
    }
    acc += a0 + a1;
    acc *= 1.0f / (float)(NCH * hgt * wid);

    // block reduction
    __shared__ float sm[THREADS / 32];
#pragma unroll
    for (int o = 16; o > 0; o >>= 1)
        acc += __shfl_down_sync(0xffffffffu, acc, o);
    if (lane == 0) sm[warp] = acc;
    __syncthreads();

    if (warp == 0) {
        acc = (lane < THREADS / 32) ? sm[lane] : 0.0f;
#pragma unroll
        for (int o = (THREADS / 64); o > 0; o >>= 1)
            acc += __shfl_down_sync(0xffffffffu, acc, o);
        if (lane == 0) atomicAdd(&g_acc, acc);
    }
}

__global__ void sel_final_kernel(const int* __restrict__ num_boxes,
                                 float* __restrict__ out) {
    int nb = 0;
#pragma unroll
    for (int bi = 0; bi < BB; bi++) nb += num_boxes[bi];
    out[0] = g_acc / (float)nb;
}

extern "C" void kernel_launch(void* const* d_in, const int* in_sizes, int n_in,
                              void* d_out, int out_size) {
    const float* y_fcn     = (const float*)d_in[0];  // [B, NCH*NCLS, H, W]
    const float* im_data   = (const float*)d_in[1];  // [B, NCH, H, W]
    // d_in[2] = im_info (unused)
    const int*   gt_boxes  = (const int*)d_in[3];    // [B, MAXB, 5]
    const int*   num_boxes = (const int*)d_in[4];    // [B]
    float*       out       = (float*)d_out;

    sel_zero_kernel<<<1, 1>>>();
    dim3 grid(NBOX, STRIPS);
    sel_strip_kernel<<<grid, THREADS>>>(y_fcn, im_data, gt_boxes, num_boxes);
    sel_final_kernel<<<1, 1>>>(num_boxes, out);
}

// round 13
// speedup vs baseline: 1.3568x; 1.0312x over previous
#include <cuda_runtime.h>

#define BB 4
#define NCH 3
#define NCLS 20
#define HH 512
#define WW 512
#define MAXB 50
#define STRIPS 8
#define THREADS 256
#define NBOX (BB * MAXB)

__device__ float g_acc = 0.0f;   // invariant: 0 at entry to every kernel_launch call

__global__ __launch_bounds__(THREADS)
void sel_strip_kernel(const float* __restrict__ y_fcn,
                      const float* __restrict__ im_data,
                      const int* __restrict__ gt_boxes,
                      const int* __restrict__ num_boxes) {
    const int boxid = blockIdx.x;
    const int strip = blockIdx.y;
    const int b = boxid / MAXB;
    const int j = boxid - b * MAXB;
    const int tid = threadIdx.x;
    const int lane = tid & 31;
    const int warp = tid >> 5;
    const int plane = HH * WW;

    if (j >= __ldg(num_boxes + b)) return;

    const int* g = gt_boxes + boxid * 5;
    const int x1 = __ldg(g), y1 = __ldg(g + 1);
    const int x2 = __ldg(g + 2), y2 = __ldg(g + 3), cls = __ldg(g + 4);
    const int hgt = y2 - y1;
    const int wid = x2 - x1;
    if (hgt <= 0 || wid <= 0) return;

    const int rows_per = (hgt + STRIPS - 1) / STRIPS;
    const int r0 = y1 + strip * rows_per;
    const int r1 = min(r0 + rows_per, y2);
    if (r0 >= r1) return;

    const int rows = r1 - r0;               // <= 32
    const float* im0 = im_data + b * NCH * plane;
    const float* yf0 = y_fcn + (b * NCLS + cls) * NCH * plane;

    // column split: scalar edges + 16B-aligned quads
    int c_lo = (x1 + 3) & ~3;
    int c_hi = x2 & ~3;
    int e1, e2, nq;
    if (c_hi > c_lo) {
        nq = (c_hi - c_lo) >> 2;
        e1 = c_lo - x1;          // 0..3 left edge px
        e2 = x2 - c_hi;          // 0..3 right edge px
    } else {
        nq = 0; e1 = wid; e2 = 0; c_hi = x1;  // all-scalar narrow box
    }

    float acc = 0.0f;

    // ---- edge pass: tid>>3 = row (rows<=32 fits 256/8), tid&7 = slot
    {
        const int rr = tid >> 3;
        const int k = tid & 7;
        if (rr < rows) {
            int col = -1;
            if (k < e1)           col = x1 + k;
            else if (k - e1 < e2) col = c_hi + (k - e1);
            if (col >= 0) {
                const int off = (r0 + rr) * WW + col;
                const float d0 = __ldg(im0 + off)             - __ldg(yf0 + off);
                const float d1 = __ldg(im0 + plane + off)     - __ldg(yf0 + plane + off);
                const float d2 = __ldg(im0 + 2 * plane + off) - __ldg(yf0 + 2 * plane + off);
                acc += d0 * d0 + d1 * d1 + d2 * d2;
            }
        }
    }

    // ---- quad pass: float4 over aligned interior
    const int totq = rows * nq;
    const unsigned unq = (unsigned)nq;
    const float4* imA = (const float4*)im0;
    const float4* imB = (const float4*)(im0 + plane);
    const float4* imC = (const float4*)(im0 + 2 * plane);
    const float4* yfA = (const float4*)yf0;
    const float4* yfB = (const float4*)(yf0 + plane);
    const float4* yfC = (const float4*)(yf0 + 2 * plane);
    float a0 = 0.0f, a1 = 0.0f;
#pragma unroll 2
    for (int idx = tid; idx < totq; idx += THREADS) {
        const unsigned rr = (unsigned)idx / unq;
        const unsigned qq = (unsigned)idx - rr * unq;
        const int q = ((r0 + (int)rr) * WW + c_lo) / 4 + (int)qq;
        const float4 pa = __ldg(imA + q), qa = __ldg(yfA + q);
        const float4 pb = __ldg(imB + q), qb = __ldg(yfB + q);
        const float4 pc = __ldg(imC + q), qc = __ldg(yfC + q);
        float t;
        t = pa.x - qa.x; a0 += t * t;  t = pa.y - qa.y; a1 += t * t;
        t = pa.z - qa.z; a0 += t * t;  t = pa.w - qa.w; a1 += t * t;
        t = pb.x - qb.x; a0 += t * t;  t = pb.y - qb.y; a1 += t * t;
        t = pb.z - qb.z; a0 += t * t;  t = pb.w - qb.w; a1 += t * t;
        t = pc.x - qc.x; a0 += t * t;  t = pc.y - qc.y; a1 += t * t;
        t = pc.z - qc.z; a0 += t * t;  t = pc.w - qc.w; a1 += t * t;
    }
    acc += a0 + a1;
    acc *= 1.0f / (float)(NCH * hgt * wid);

    // block reduction
    __shared__ float sm[THREADS / 32];
#pragma unroll
    for (int o = 16; o > 0; o >>= 1)
        acc += __shfl_down_sync(0xffffffffu, acc, o);
    if (lane == 0) sm[warp] = acc;
    __syncthreads();

    if (warp == 0) {
        acc = (lane < THREADS / 32) ? sm[lane] : 0.0f;
#pragma unroll
        for (int o = (THREADS / 64); o > 0; o >>= 1)
            acc += __shfl_down_sync(0xffffffffu, acc, o);
        if (lane == 0) atomicAdd(&g_acc, acc);
    }
}

__global__ void sel_final_kernel(const int* __restrict__ num_boxes,
                                 float* __restrict__ out) {
    int nb = 0;
#pragma unroll
    for (int bi = 0; bi < BB; bi++) nb += num_boxes[bi];
    out[0] = g_acc / (float)nb;
    g_acc = 0.0f;   // re-establish invariant for the next invocation
}

extern "C" void kernel_launch(void* const* d_in, const int* in_sizes, int n_in,
                              void* d_out, int out_size) {
    const float* y_fcn     = (const float*)d_in[0];  // [B, NCH*NCLS, H, W]
    const float* im_data   = (const float*)d_in[1];  // [B, NCH, H, W]
    // d_in[2] = im_info (unused)
    const int*   gt_boxes  = (const int*)d_in[3];    // [B, MAXB, 5]
    const int*   num_boxes = (const int*)d_in[4];    // [B]
    float*       out       = (float*)d_out;

    dim3 grid(NBOX, STRIPS);
    sel_strip_kernel<<<grid, THREADS>>>(y_fcn, im_data, gt_boxes, num_boxes);
    sel_final_kernel<<<1, 1>>>(num_boxes, out);
}